// round 14
// baseline (speedup 1.0000x reference)
#include <cuda_runtime.h>
#include <cuda_fp16.h>
#include <math.h>
#include <stdint.h>

#define SS 2048
#define DD 512
#define NB 4
#define KC 64
#define NTHREADS 256                     // 8 warps, 2(m) x 4(n), warp tile 64x64
#define TM 128                           // CTA tile m
#define TN 256                           // CTA tile n
#define XTILE_BYTES (TM * 128)           // 16384 (swizzled 128B rows)
#define YTILE_BYTES (TN * 128)           // 32768
#define STAGE_BYTES (XTILE_BYTES + YTILE_BYTES)  // 49152
#define NSTAGE 4
#define SMEM_PIPE (NSTAGE * STAGE_BYTES) // 196608
#define SMEM_DYN (SMEM_PIPE + 512)

// ---------------- scratch (allocation-free device globals, fp16) ----------
__device__ __half g_W[(size_t)NB * SS * SS];    // 32 MB weight matrix
__device__ __half g_Ah[(size_t)NB * SS * SS];   // 32 MB rounded A
__device__ __half g_Vh[(size_t)NB * SS * DD];   // 8 MB rounded V
__device__ __half g_VTh[(size_t)NB * DD * SS];  // 8 MB rounded V^T [d][s]
__device__ __half g_Mh[(size_t)NB * SS * DD];   // 8 MB rounded M
__device__ float g_v2[NB * SS];
__device__ float g_m2part[2][NB * SS];          // per-n0-block partial |M|^2
__device__ float g_l1part[8][NB * SS];          // per-j-block partial l1 sums

// ---------------- helpers ----------------
__device__ __forceinline__ uint32_t smem_u32(const void* p) {
    uint32_t a;
    asm("{ .reg .u64 t; cvta.to.shared.u64 t, %1; cvt.u32.u64 %0, t; }"
        : "=r"(a) : "l"(p));
    return a;
}
__device__ __forceinline__ void cp16(uint32_t saddr, const void* gaddr) {
    asm volatile("cp.async.cg.shared.global [%0], [%1], 16;"
                 :: "r"(saddr), "l"(gaddr) : "memory");
}
__device__ __forceinline__ void cp_commit() {
    asm volatile("cp.async.commit_group;" ::: "memory");
}
template <int N>
__device__ __forceinline__ void cp_wait() {
    asm volatile("cp.async.wait_group %0;" :: "n"(N) : "memory");
}
__device__ __forceinline__ void ldsm4(uint32_t* r, uint32_t addr) {
    asm volatile("ldmatrix.sync.aligned.m8n8.x4.shared.b16 {%0,%1,%2,%3}, [%4];"
                 : "=r"(r[0]), "=r"(r[1]), "=r"(r[2]), "=r"(r[3]) : "r"(addr));
}
__device__ __forceinline__ void mma_f16(float* c, const uint32_t* a, const uint32_t* b) {
    asm volatile(
        "mma.sync.aligned.m16n8k16.row.col.f32.f16.f16.f32 "
        "{%0,%1,%2,%3}, {%4,%5,%6,%7}, {%8,%9}, {%0,%1,%2,%3};"
        : "+f"(c[0]), "+f"(c[1]), "+f"(c[2]), "+f"(c[3])
        : "r"(a[0]), "r"(a[1]), "r"(a[2]), "r"(a[3]), "r"(b[0]), "r"(b[1]));
}

// ---------------------------------------------------------------------------
// Issue one stage: TMx64 X tile + TNx64 Y tile via cp.async, XOR-swizzled
// 128B rows (unit col ^= row&7). 12 x 16B per thread.
// ---------------------------------------------------------------------------
__device__ __forceinline__ void issue_stage(const __half* __restrict__ X,
                                            const __half* __restrict__ Y,
                                            int ldx, int ldy, int m0, int n0,
                                            int k0, uint32_t sbuf, int tid) {
#pragma unroll
    for (int p = 0; p < TM * 8 / NTHREADS; ++p) {       // 4
        int idx = tid + p * NTHREADS;
        int row = idx >> 3, q = idx & 7;
        cp16(sbuf + row * 128 + ((q ^ (row & 7)) << 4),
             X + (size_t)(m0 + row) * ldx + k0 + q * 8);
    }
    uint32_t ybuf = sbuf + XTILE_BYTES;
#pragma unroll
    for (int p = 0; p < TN * 8 / NTHREADS; ++p) {       // 8
        int idx = tid + p * NTHREADS;
        int row = idx >> 3, q = idx & 7;
        cp16(ybuf + row * 128 + ((q ^ (row & 7)) << 4),
             Y + (size_t)(n0 + row) * ldy + k0 + q * 8);
    }
    cp_commit();
}

// ---------------------------------------------------------------------------
// Load one k16 slice of fragments: 4 ldsm.x4 (A, 64 m-rows) + 4 ldsm.x4
// (B, 64 n-rows -> 8 nf).
// ---------------------------------------------------------------------------
__device__ __forceinline__ void ld_frags(uint32_t xs, uint32_t ys, int ks,
                                         const uint32_t* arowb, const uint32_t* browb,
                                         uint32_t ua0, uint32_t ub0, uint32_t lr,
                                         uint32_t af[4][4], uint32_t bf[8][2]) {
    uint32_t ua = (((ua0 + 2 * ks) ^ lr) << 4);
    uint32_t ub = (((ub0 + 2 * ks) ^ lr) << 4);
#pragma unroll
    for (int mf = 0; mf < 4; ++mf) ldsm4(af[mf], xs + arowb[mf] + ua);
#pragma unroll
    for (int p = 0; p < 4; ++p) {
        uint32_t r[4];
        ldsm4(r, ys + browb[p] + ub);
        bf[2 * p][0] = r[0];
        bf[2 * p][1] = r[1];
        bf[2 * p + 1][0] = r[2];
        bf[2 * p + 1][1] = r[3];
    }
}

// ---------------------------------------------------------------------------
// One KC=64 chunk: 4 k16 slices, fragment double-buffered (next slice's
// LDSMs issue during current slice's 32 MMAs).
// ---------------------------------------------------------------------------
__device__ __forceinline__ void compute_chunk(uint32_t sb, float acc[4][8][4],
                                              const uint32_t* arowb,
                                              const uint32_t* browb,
                                              uint32_t ua0, uint32_t ub0,
                                              uint32_t lr) {
    uint32_t ys = sb + XTILE_BYTES;
    uint32_t af[2][4][4], bf[2][8][2];
    ld_frags(sb, ys, 0, arowb, browb, ua0, ub0, lr, af[0], bf[0]);
#pragma unroll
    for (int ks = 0; ks < 4; ++ks) {
        int cur = ks & 1, nxt = cur ^ 1;
        if (ks < 3)
            ld_frags(sb, ys, ks + 1, arowb, browb, ua0, ub0, lr, af[nxt], bf[nxt]);
#pragma unroll
        for (int mf = 0; mf < 4; ++mf)
#pragma unroll
            for (int nf = 0; nf < 8; ++nf)
                mma_f16(acc[mf][nf], af[cur][mf], bf[cur][nf]);
    }
}

// ---------------------------------------------------------------------------
// 4-buffer cp.async mainloop (prefetch depth 3, 1 sync/chunk).
// ---------------------------------------------------------------------------
__device__ __forceinline__ void mainloop(const __half* X, const __half* Y,
                                         int ldx, int ldy, int nch,
                                         int m0, int n0, uint32_t* dyn,
                                         float acc[4][8][4], int tid,
                                         const uint32_t* arowb,
                                         const uint32_t* browb,
                                         uint32_t ua0, uint32_t ub0, uint32_t lr) {
    uint32_t sb = smem_u32(dyn);
    issue_stage(X, Y, ldx, ldy, m0, n0, 0, sb, tid);
    issue_stage(X, Y, ldx, ldy, m0, n0, KC, sb + STAGE_BYTES, tid);
    issue_stage(X, Y, ldx, ldy, m0, n0, 2 * KC, sb + 2 * STAGE_BYTES, tid);
    for (int ch = 0; ch < nch; ++ch) {
        cp_wait<2>();
        __syncthreads();
        if (ch + 3 < nch)
            issue_stage(X, Y, ldx, ldy, m0, n0, (ch + 3) * KC,
                        sb + ((ch + 3) & 3) * STAGE_BYTES, tid);
        else
            cp_commit();
        compute_chunk(sb + (ch & 3) * STAGE_BYTES, acc, arowb, browb, ua0, ub0, lr);
    }
}

// ---------------------------------------------------------------------------
// Elementwise round fp32 -> fp16 (grid-stride, float4 in).
// ---------------------------------------------------------------------------
__global__ void round_kernel(const float* __restrict__ in, __half* __restrict__ out,
                             int n4) {
    int i = blockIdx.x * blockDim.x + threadIdx.x;
    int stride = gridDim.x * blockDim.x;
    for (; i < n4; i += stride) {
        float4 v = reinterpret_cast<const float4*>(in)[i];
        __half2* o = reinterpret_cast<__half2*>(out) + 2 * i;
        o[0] = __floats2half2_rn(v.x, v.y);
        o[1] = __floats2half2_rn(v.z, v.w);
    }
}

// ---------------------------------------------------------------------------
// Fused V prep: g_Vh = round(V); g_VTh[d][s] = round(V[s][d]); g_v2.
// ---------------------------------------------------------------------------
__global__ void prepV_kernel(const float* __restrict__ V) {
    __shared__ float t[32][33];
    int b = blockIdx.y;
    int s0 = blockIdx.x * 32;
    const float* Vp = V + (size_t)b * SS * DD;
    __half* Vh = g_Vh + (size_t)b * SS * DD;
    __half* Tp = g_VTh + (size_t)b * DD * SS;
    int tx = threadIdx.x & 31, ty = threadIdx.x >> 5;
    float vsum[4] = {0.f, 0.f, 0.f, 0.f};
    for (int dt = 0; dt < DD / 32; ++dt) {
#pragma unroll
        for (int j = 0; j < 4; ++j) {
            int i = ty + 8 * j;
            float v = Vp[(size_t)(s0 + i) * DD + dt * 32 + tx];
            __half h = __float2half_rn(v);
            float vr = __half2float(h);
            t[i][tx] = vr;
            vsum[j] += vr * vr;
            Vh[(size_t)(s0 + i) * DD + dt * 32 + tx] = h;
        }
        __syncthreads();
#pragma unroll
        for (int j = 0; j < 4; ++j) {
            int i = ty + 8 * j;
            Tp[(size_t)(dt * 32 + i) * SS + s0 + tx] = __float2half_rn(t[tx][i]);
        }
        __syncthreads();
    }
#pragma unroll
    for (int j = 0; j < 4; ++j) {
#pragma unroll
        for (int o = 16; o > 0; o >>= 1)
            vsum[j] += __shfl_down_sync(0xffffffffu, vsum[j], o);
        if (tx == 0) g_v2[b * SS + s0 + ty + 8 * j] = vsum[j];
    }
}

// ---------------------------------------------------------------------------
// GEMM: out[m,n] = scale(m) * sum_k X[m,k]*VTh[n,k]   (N = DD = 512)
// CTA 128x256, warp tile 64x64.
// ---------------------------------------------------------------------------
__global__ void __launch_bounds__(NTHREADS, 1)
gemm_tc(float* __restrict__ C, int use_w, int use_l1, int final_out) {
    extern __shared__ uint32_t dyn[];
    float* s_red = (float*)((char*)dyn + SMEM_PIPE);
    int tid = threadIdx.x;
    int wid = tid >> 5, lane = tid & 31;
    int wm = wid >> 2, wn = wid & 3;          // 2 x 4 warp grid
    int g = lane >> 2, tg = lane & 3;
    uint32_t q = lane >> 3, lr = lane & 7;
    int b = blockIdx.z;
    int n0 = blockIdx.x * TN, m0 = blockIdx.y * TM;
    const __half* X = (use_w ? g_W : g_Ah) + (size_t)b * SS * SS;
    const __half* Y = g_VTh + (size_t)b * DD * SS;

    uint32_t arowb[4], browb[4];
#pragma unroll
    for (int mf = 0; mf < 4; ++mf)
        arowb[mf] = (wm * 64 + mf * 16 + (q & 1) * 8 + lr) * 128;
#pragma unroll
    for (int p = 0; p < 4; ++p)
        browb[p] = (wn * 64 + p * 16 + (q >> 1) * 8 + lr) * 128;
    uint32_t ua0 = q >> 1, ub0 = q & 1;

    float acc[4][8][4];
#pragma unroll
    for (int i = 0; i < 4; ++i)
#pragma unroll
        for (int j = 0; j < 8; ++j)
#pragma unroll
            for (int e = 0; e < 4; ++e) acc[i][j][e] = 0.0f;

    mainloop(X, Y, SS, SS, SS / KC, m0, n0, dyn, acc, tid,
             arowb, browb, ua0, ub0, lr);

    float s1v[4], s2v[4];
    if (use_l1) {
        if (tid < TM) {
            float s = 0.0f;
#pragma unroll
            for (int p = 0; p < 8; ++p) s += g_l1part[p][b * SS + m0 + tid];
            s_red[tid] = s;
        }
        __syncthreads();
#pragma unroll
        for (int mf = 0; mf < 4; ++mf) {
            int rr = wm * 64 + mf * 16 + g;
            s1v[mf] = 1.0f / fmaxf(s_red[rr], 1e-12f);
            s2v[mf] = 1.0f / fmaxf(s_red[rr + 8], 1e-12f);
        }
        __syncthreads();
    } else {
#pragma unroll
        for (int mf = 0; mf < 4; ++mf) { s1v[mf] = 1.0f; s2v[mf] = 1.0f; }
    }

    if (final_out) {
        float* Co = C + (size_t)b * SS * DD;
#pragma unroll
        for (int mf = 0; mf < 4; ++mf) {
            int r1 = m0 + wm * 64 + mf * 16 + g;
            int r2 = r1 + 8;
#pragma unroll
            for (int nf = 0; nf < 8; ++nf) {
                int col = n0 + wn * 64 + nf * 8 + 2 * tg;
                *reinterpret_cast<float2*>(Co + (size_t)r1 * DD + col) =
                    make_float2(acc[mf][nf][0] * s1v[mf], acc[mf][nf][1] * s1v[mf]);
                *reinterpret_cast<float2*>(Co + (size_t)r2 * DD + col) =
                    make_float2(acc[mf][nf][2] * s2v[mf], acc[mf][nf][3] * s2v[mf]);
            }
        }
    } else {
        if (tid < TM) s_red[tid] = 0.0f;
        __syncthreads();
        __half* Mo = g_Mh + (size_t)b * SS * DD;
#pragma unroll
        for (int mf = 0; mf < 4; ++mf) {
            int r1 = m0 + wm * 64 + mf * 16 + g;
            int r2 = r1 + 8;
            float a1s = 0.0f, a2s = 0.0f;
#pragma unroll
            for (int nf = 0; nf < 8; ++nf) {
                int col = n0 + wn * 64 + nf * 8 + 2 * tg;
                __half2 h1 = __floats2half2_rn(acc[mf][nf][0] * s1v[mf],
                                               acc[mf][nf][1] * s1v[mf]);
                __half2 h2 = __floats2half2_rn(acc[mf][nf][2] * s2v[mf],
                                               acc[mf][nf][3] * s2v[mf]);
                *reinterpret_cast<__half2*>(Mo + (size_t)r1 * DD + col) = h1;
                *reinterpret_cast<__half2*>(Mo + (size_t)r2 * DD + col) = h2;
                float2 f1 = __half22float2(h1), f2 = __half22float2(h2);
                a1s += f1.x * f1.x + f1.y * f1.y;
                a2s += f2.x * f2.x + f2.y * f2.y;
            }
            a1s += __shfl_xor_sync(0xffffffffu, a1s, 1);
            a1s += __shfl_xor_sync(0xffffffffu, a1s, 2);
            a2s += __shfl_xor_sync(0xffffffffu, a2s, 1);
            a2s += __shfl_xor_sync(0xffffffffu, a2s, 2);
            if (tg == 0) {
                atomicAdd(&s_red[wm * 64 + mf * 16 + g], a1s);
                atomicAdd(&s_red[wm * 64 + mf * 16 + g + 8], a2s);
            }
        }
        __syncthreads();
        if (tid < TM)
            g_m2part[blockIdx.x][b * SS + m0 + tid] = s_red[tid];
    }
}

// ---------------------------------------------------------------------------
// W[i,j] = fp16(Ah[i,j]/(sqrt(max(m2[i]+v2[j]-2*Mh_i.Vh_j,0))+0.01));
// CTA 128(i) x 256(j); writes per-j-block l1 partials.
// ---------------------------------------------------------------------------
__global__ void __launch_bounds__(NTHREADS, 1)
wdist_tc() {
    extern __shared__ uint32_t dyn[];
    float* s_red = (float*)((char*)dyn + SMEM_PIPE);
    int tid = threadIdx.x;
    int wid = tid >> 5, lane = tid & 31;
    int wm = wid >> 2, wn = wid & 3;
    int g = lane >> 2, tg = lane & 3;
    uint32_t q = lane >> 3, lr = lane & 7;
    int b = blockIdx.z;
    int j0 = blockIdx.x * TN, i0 = blockIdx.y * TM;
    const __half* Mp = g_Mh + (size_t)b * SS * DD;
    const __half* Vp = g_Vh + (size_t)b * SS * DD;
    const __half* Ap = g_Ah + (size_t)b * SS * SS;
    __half* Wp = g_W + (size_t)b * SS * SS;
    const float* v2p = g_v2 + b * SS;

    uint32_t arowb[4], browb[4];
#pragma unroll
    for (int mf = 0; mf < 4; ++mf)
        arowb[mf] = (wm * 64 + mf * 16 + (q & 1) * 8 + lr) * 128;
#pragma unroll
    for (int p = 0; p < 4; ++p)
        browb[p] = (wn * 64 + p * 16 + (q >> 1) * 8 + lr) * 128;
    uint32_t ua0 = q >> 1, ub0 = q & 1;

    float acc[4][8][4];
#pragma unroll
    for (int i = 0; i < 4; ++i)
#pragma unroll
        for (int j = 0; j < 8; ++j)
#pragma unroll
            for (int e = 0; e < 4; ++e) acc[i][j][e] = 0.0f;

    mainloop(Mp, Vp, DD, DD, DD / KC, i0, j0, dyn, acc, tid,
             arowb, browb, ua0, ub0, lr);

    if (tid < TM) {
        float s = g_m2part[0][b * SS + i0 + tid] + g_m2part[1][b * SS + i0 + tid];
        s_red[tid] = s;
    }
    __syncthreads();
    float m21v[4], m22v[4];
#pragma unroll
    for (int mf = 0; mf < 4; ++mf) {
        int rr = wm * 64 + mf * 16 + g;
        m21v[mf] = s_red[rr];
        m22v[mf] = s_red[rr + 8];
    }
    __syncthreads();
    if (tid < TM) s_red[tid] = 0.0f;
    __syncthreads();

#pragma unroll
    for (int mf = 0; mf < 4; ++mf) {
        int r1 = i0 + wm * 64 + mf * 16 + g;
        int r2 = r1 + 8;
        float rs1 = 0.0f, rs2 = 0.0f;
#pragma unroll
        for (int nf = 0; nf < 8; ++nf) {
            int jj = j0 + wn * 64 + nf * 8 + 2 * tg;
            float v2a = v2p[jj], v2b = v2p[jj + 1];
            float2 a1 = __half22float2(
                *reinterpret_cast<const __half2*>(Ap + (size_t)r1 * SS + jj));
            float2 a2 = __half22float2(
                *reinterpret_cast<const __half2*>(Ap + (size_t)r2 * SS + jj));
            float d;
            d = sqrtf(fmaxf(m21v[mf] + v2a - 2.0f * acc[mf][nf][0], 0.0f));
            float w0 = a1.x * __frcp_rn(d + 0.01f);
            d = sqrtf(fmaxf(m21v[mf] + v2b - 2.0f * acc[mf][nf][1], 0.0f));
            float w1 = a1.y * __frcp_rn(d + 0.01f);
            d = sqrtf(fmaxf(m22v[mf] + v2a - 2.0f * acc[mf][nf][2], 0.0f));
            float w2 = a2.x * __frcp_rn(d + 0.01f);
            d = sqrtf(fmaxf(m22v[mf] + v2b - 2.0f * acc[mf][nf][3], 0.0f));
            float w3 = a2.y * __frcp_rn(d + 0.01f);
            __half2 h1 = __floats2half2_rn(w0, w1);
            __half2 h2 = __floats2half2_rn(w2, w3);
            float2 f1 = __half22float2(h1), f2 = __half22float2(h2);
            rs1 += fabsf(f1.x) + fabsf(f1.y);
            rs2 += fabsf(f2.x) + fabsf(f2.y);
            *reinterpret_cast<__half2*>(Wp + (size_t)r1 * SS + jj) = h1;
            *reinterpret_cast<__half2*>(Wp + (size_t)r2 * SS + jj) = h2;
        }
        rs1 += __shfl_xor_sync(0xffffffffu, rs1, 1);
        rs1 += __shfl_xor_sync(0xffffffffu, rs1, 2);
        rs2 += __shfl_xor_sync(0xffffffffu, rs2, 1);
        rs2 += __shfl_xor_sync(0xffffffffu, rs2, 2);
        if (tg == 0) {
            atomicAdd(&s_red[wm * 64 + mf * 16 + g], rs1);
            atomicAdd(&s_red[wm * 64 + mf * 16 + g + 8], rs2);
        }
    }
    __syncthreads();
    if (tid < TM)
        g_l1part[blockIdx.x][b * SS + i0 + tid] = s_red[tid];
}

// ---------------------------------------------------------------------------
extern "C" void kernel_launch(void* const* d_in, const int* in_sizes, int n_in,
                              void* d_out, int out_size) {
    const float* A = (const float*)d_in[0];  // (4, 2048, 2048)
    const float* V = (const float*)d_in[1];  // (4, 2048, 512)
    float* M = (float*)d_out;                // (4, 2048, 512)

    cudaFuncSetAttribute(gemm_tc, cudaFuncAttributeMaxDynamicSharedMemorySize, SMEM_DYN);
    cudaFuncSetAttribute(wdist_tc, cudaFuncAttributeMaxDynamicSharedMemorySize, SMEM_DYN);

    __half* g_Ah_p;  cudaGetSymbolAddress((void**)&g_Ah_p, g_Ah);

    dim3 ggrid(DD / TN, SS / TM, NB);   // (2, 16, 4) = 128 CTAs
    dim3 wgrid(SS / TN, SS / TM, NB);   // (8, 16, 4) = 512 CTAs

    int nA4 = NB * SS * SS / 4;
    round_kernel<<<1024, 256>>>(A, g_Ah_p, nA4 / 2);                     // #1
    round_kernel<<<1024, 256>>>(A + (size_t)nA4 / 2 * 4,
                                g_Ah_p + (size_t)nA4 / 2 * 4, nA4 / 2);  // #2
    prepV_kernel<<<dim3(SS / 32, NB), 256>>>(V);                         // #3
    gemm_tc<<<ggrid, NTHREADS, SMEM_DYN>>>(M, 0, 0, 0);                  // #4 (profiled)
    for (int it = 0; it < 3; ++it) {
        wdist_tc<<<wgrid, NTHREADS, SMEM_DYN>>>();
        gemm_tc<<<ggrid, NTHREADS, SMEM_DYN>>>(M, 1, 1, it == 2);
    }
}

// round 16
// speedup vs baseline: 1.1911x; 1.1911x over previous
#include <cuda_runtime.h>
#include <cuda_fp16.h>
#include <math.h>
#include <stdint.h>

#define SS 2048
#define DD 512
#define NB 4
#define KC 64
#define NTHREADS 256

// ---- gemm config (R13): CTA 128x256, warp tile 64x64, XOR-swizzled 128B rows
#define G_TM 128
#define G_TN 256
#define G_XTILE (G_TM * 128)                 // 16384
#define G_YTILE (G_TN * 128)                 // 32768
#define G_STAGE (G_XTILE + G_YTILE)          // 49152
#define G_NSTAGE 4
#define G_PIPE (G_NSTAGE * G_STAGE)          // 196608
#define G_SMEM (G_PIPE + 512)

// ---- wdist config (R12): CTA 128x128, warp tile 64x32, padded LDSH=72
#define W_LDSH 72
#define W_XTILE (128 * W_LDSH * 2)           // 18432
#define W_STAGE (2 * W_XTILE)                // 36864
#define W_NSTAGE 3
#define W_PIPE (W_NSTAGE * W_STAGE)          // 110592
#define W_SMEM (W_PIPE + 512)

// ---------------- scratch (allocation-free device globals, fp16) ----------
__device__ __half g_W[(size_t)NB * SS * SS];    // 32 MB weight matrix
__device__ __half g_Ah[(size_t)NB * SS * SS];   // 32 MB rounded A
__device__ __half g_Vh[(size_t)NB * SS * DD];   // 8 MB rounded V
__device__ __half g_VTh[(size_t)NB * DD * SS];  // 8 MB rounded V^T [d][s]
__device__ __half g_Mh[(size_t)NB * SS * DD];   // 8 MB rounded M
__device__ float g_v2[NB * SS];
__device__ float g_m2part[2][NB * SS];          // gemm: 2 n-blocks (TN=256)
__device__ float g_l1part[16][NB * SS];         // wdist: 16 j-blocks (TN=128)

// ---------------- helpers ----------------
__device__ __forceinline__ uint32_t smem_u32(const void* p) {
    uint32_t a;
    asm("{ .reg .u64 t; cvta.to.shared.u64 t, %1; cvt.u32.u64 %0, t; }"
        : "=r"(a) : "l"(p));
    return a;
}
__device__ __forceinline__ void cp16(uint32_t saddr, const void* gaddr) {
    asm volatile("cp.async.cg.shared.global [%0], [%1], 16;"
                 :: "r"(saddr), "l"(gaddr) : "memory");
}
__device__ __forceinline__ void cp_commit() {
    asm volatile("cp.async.commit_group;" ::: "memory");
}
template <int N>
__device__ __forceinline__ void cp_wait() {
    asm volatile("cp.async.wait_group %0;" :: "n"(N) : "memory");
}
__device__ __forceinline__ void ldsm4(uint32_t* r, uint32_t addr) {
    asm volatile("ldmatrix.sync.aligned.m8n8.x4.shared.b16 {%0,%1,%2,%3}, [%4];"
                 : "=r"(r[0]), "=r"(r[1]), "=r"(r[2]), "=r"(r[3]) : "r"(addr));
}
__device__ __forceinline__ void mma_f16(float* c, const uint32_t* a, const uint32_t* b) {
    asm volatile(
        "mma.sync.aligned.m16n8k16.row.col.f32.f16.f16.f32 "
        "{%0,%1,%2,%3}, {%4,%5,%6,%7}, {%8,%9}, {%0,%1,%2,%3};"
        : "+f"(c[0]), "+f"(c[1]), "+f"(c[2]), "+f"(c[3])
        : "r"(a[0]), "r"(a[1]), "r"(a[2]), "r"(a[3]), "r"(b[0]), "r"(b[1]));
}

// ===========================================================================
// GEMM-side pipeline (R13): XOR-swizzle, warp tile 64x64, frag double-buffer
// ===========================================================================
__device__ __forceinline__ void g_issue(const __half* __restrict__ X,
                                        const __half* __restrict__ Y,
                                        int ldx, int ldy, int m0, int n0,
                                        int k0, uint32_t sbuf, int tid) {
#pragma unroll
    for (int p = 0; p < G_TM * 8 / NTHREADS; ++p) {
        int idx = tid + p * NTHREADS;
        int row = idx >> 3, q = idx & 7;
        cp16(sbuf + row * 128 + ((q ^ (row & 7)) << 4),
             X + (size_t)(m0 + row) * ldx + k0 + q * 8);
    }
    uint32_t ybuf = sbuf + G_XTILE;
#pragma unroll
    for (int p = 0; p < G_TN * 8 / NTHREADS; ++p) {
        int idx = tid + p * NTHREADS;
        int row = idx >> 3, q = idx & 7;
        cp16(ybuf + row * 128 + ((q ^ (row & 7)) << 4),
             Y + (size_t)(n0 + row) * ldy + k0 + q * 8);
    }
    cp_commit();
}

__device__ __forceinline__ void g_ldfrags(uint32_t xs, uint32_t ys, int ks,
                                          const uint32_t* arowb, const uint32_t* browb,
                                          uint32_t ua0, uint32_t ub0, uint32_t lr,
                                          uint32_t af[4][4], uint32_t bf[8][2]) {
    uint32_t ua = (((ua0 + 2 * ks) ^ lr) << 4);
    uint32_t ub = (((ub0 + 2 * ks) ^ lr) << 4);
#pragma unroll
    for (int mf = 0; mf < 4; ++mf) ldsm4(af[mf], xs + arowb[mf] + ua);
#pragma unroll
    for (int p = 0; p < 4; ++p) {
        uint32_t r[4];
        ldsm4(r, ys + browb[p] + ub);
        bf[2 * p][0] = r[0];
        bf[2 * p][1] = r[1];
        bf[2 * p + 1][0] = r[2];
        bf[2 * p + 1][1] = r[3];
    }
}

__device__ __forceinline__ void g_chunk(uint32_t sb, float acc[4][8][4],
                                        const uint32_t* arowb, const uint32_t* browb,
                                        uint32_t ua0, uint32_t ub0, uint32_t lr) {
    uint32_t ys = sb + G_XTILE;
    uint32_t af[2][4][4], bf[2][8][2];
    g_ldfrags(sb, ys, 0, arowb, browb, ua0, ub0, lr, af[0], bf[0]);
#pragma unroll
    for (int ks = 0; ks < 4; ++ks) {
        int cur = ks & 1, nxt = cur ^ 1;
        if (ks < 3)
            g_ldfrags(sb, ys, ks + 1, arowb, browb, ua0, ub0, lr, af[nxt], bf[nxt]);
#pragma unroll
        for (int mf = 0; mf < 4; ++mf)
#pragma unroll
            for (int nf = 0; nf < 8; ++nf)
                mma_f16(acc[mf][nf], af[cur][mf], bf[cur][nf]);
    }
}

// ===========================================================================
// wdist-side pipeline (R12): padded LDSH=72, warp tile 64x32
// ===========================================================================
__device__ __forceinline__ void w_issue(const __half* __restrict__ X,
                                        const __half* __restrict__ Y,
                                        int ldx, int ldy, int m0, int n0,
                                        int k0, uint32_t sbuf, int tid) {
#pragma unroll
    for (int p = 0; p < 4; ++p) {
        int idx = tid + p * NTHREADS;
        int row = idx >> 3, q = idx & 7;
        cp16(sbuf + (row * W_LDSH + q * 8) * 2,
             X + (size_t)(m0 + row) * ldx + k0 + q * 8);
    }
    uint32_t ybuf = sbuf + W_XTILE;
#pragma unroll
    for (int p = 0; p < 4; ++p) {
        int idx = tid + p * NTHREADS;
        int row = idx >> 3, q = idx & 7;
        cp16(ybuf + (row * W_LDSH + q * 8) * 2,
             Y + (size_t)(n0 + row) * ldy + k0 + q * 8);
    }
    cp_commit();
}

__device__ __forceinline__ void w_chunk(uint32_t sb, float acc[4][4][4],
                                        const uint32_t* aoff, const uint32_t* boff) {
    uint32_t ys = sb + W_XTILE;
#pragma unroll
    for (int ks = 0; ks < 4; ++ks) {
        uint32_t kb = ks * 16 * 2;
        uint32_t af[4][4], bf[4][2];
#pragma unroll
        for (int mf = 0; mf < 4; ++mf) ldsm4(af[mf], sb + aoff[mf] + kb);
#pragma unroll
        for (int p = 0; p < 2; ++p) {
            uint32_t r[4];
            ldsm4(r, ys + boff[p] + kb);
            bf[2 * p][0] = r[0];
            bf[2 * p][1] = r[1];
            bf[2 * p + 1][0] = r[2];
            bf[2 * p + 1][1] = r[3];
        }
#pragma unroll
        for (int mf = 0; mf < 4; ++mf)
#pragma unroll
            for (int nf = 0; nf < 4; ++nf)
                mma_f16(acc[mf][nf], af[mf], bf[nf]);
    }
}

// ---------------------------------------------------------------------------
// Elementwise round fp32 -> fp16 (grid-stride, float4 in).
// ---------------------------------------------------------------------------
__global__ void round_kernel(const float* __restrict__ in, __half* __restrict__ out,
                             int n4) {
    int i = blockIdx.x * blockDim.x + threadIdx.x;
    int stride = gridDim.x * blockDim.x;
    for (; i < n4; i += stride) {
        float4 v = reinterpret_cast<const float4*>(in)[i];
        __half2* o = reinterpret_cast<__half2*>(out) + 2 * i;
        o[0] = __floats2half2_rn(v.x, v.y);
        o[1] = __floats2half2_rn(v.z, v.w);
    }
}

// ---------------------------------------------------------------------------
// Fused V prep: g_Vh = round(V); g_VTh[d][s] = round(V[s][d]); g_v2.
// ---------------------------------------------------------------------------
__global__ void prepV_kernel(const float* __restrict__ V) {
    __shared__ float t[32][33];
    int b = blockIdx.y;
    int s0 = blockIdx.x * 32;
    const float* Vp = V + (size_t)b * SS * DD;
    __half* Vh = g_Vh + (size_t)b * SS * DD;
    __half* Tp = g_VTh + (size_t)b * DD * SS;
    int tx = threadIdx.x & 31, ty = threadIdx.x >> 5;
    float vsum[4] = {0.f, 0.f, 0.f, 0.f};
    for (int dt = 0; dt < DD / 32; ++dt) {
#pragma unroll
        for (int j = 0; j < 4; ++j) {
            int i = ty + 8 * j;
            float v = Vp[(size_t)(s0 + i) * DD + dt * 32 + tx];
            __half h = __float2half_rn(v);
            float vr = __half2float(h);
            t[i][tx] = vr;
            vsum[j] += vr * vr;
            Vh[(size_t)(s0 + i) * DD + dt * 32 + tx] = h;
        }
        __syncthreads();
#pragma unroll
        for (int j = 0; j < 4; ++j) {
            int i = ty + 8 * j;
            Tp[(size_t)(dt * 32 + i) * SS + s0 + tx] = __float2half_rn(t[tx][i]);
        }
        __syncthreads();
    }
#pragma unroll
    for (int j = 0; j < 4; ++j) {
#pragma unroll
        for (int o = 16; o > 0; o >>= 1)
            vsum[j] += __shfl_down_sync(0xffffffffu, vsum[j], o);
        if (tx == 0) g_v2[b * SS + s0 + ty + 8 * j] = vsum[j];
    }
}

// ---------------------------------------------------------------------------
// GEMM (R13 shape): out[m,n] = scale(m) * sum_k X[m,k]*VTh[n,k]
// ---------------------------------------------------------------------------
__global__ void __launch_bounds__(NTHREADS, 1)
gemm_tc(float* __restrict__ C, int use_w, int use_l1, int final_out) {
    extern __shared__ uint32_t dyn[];
    float* s_red = (float*)((char*)dyn + G_PIPE);
    int tid = threadIdx.x;
    int wid = tid >> 5, lane = tid & 31;
    int wm = wid >> 2, wn = wid & 3;
    int g = lane >> 2, tg = lane & 3;
    uint32_t q = lane >> 3, lr = lane & 7;
    int b = blockIdx.z;
    int n0 = blockIdx.x * G_TN, m0 = blockIdx.y * G_TM;
    const __half* X = (use_w ? g_W : g_Ah) + (size_t)b * SS * SS;
    const __half* Y = g_VTh + (size_t)b * DD * SS;

    uint32_t arowb[4], browb[4];
#pragma unroll
    for (int mf = 0; mf < 4; ++mf)
        arowb[mf] = (wm * 64 + mf * 16 + (q & 1) * 8 + lr) * 128;
#pragma unroll
    for (int p = 0; p < 4; ++p)
        browb[p] = (wn * 64 + p * 16 + (q >> 1) * 8 + lr) * 128;
    uint32_t ua0 = q >> 1, ub0 = q & 1;

    float acc[4][8][4];
#pragma unroll
    for (int i = 0; i < 4; ++i)
#pragma unroll
        for (int j = 0; j < 8; ++j)
#pragma unroll
            for (int e = 0; e < 4; ++e) acc[i][j][e] = 0.0f;

    {
        uint32_t sb = smem_u32(dyn);
        g_issue(X, Y, SS, SS, m0, n0, 0, sb, tid);
        g_issue(X, Y, SS, SS, m0, n0, KC, sb + G_STAGE, tid);
        g_issue(X, Y, SS, SS, m0, n0, 2 * KC, sb + 2 * G_STAGE, tid);
        int nch = SS / KC;
        for (int ch = 0; ch < nch; ++ch) {
            cp_wait<2>();
            __syncthreads();
            if (ch + 3 < nch)
                g_issue(X, Y, SS, SS, m0, n0, (ch + 3) * KC,
                        sb + ((ch + 3) & 3) * G_STAGE, tid);
            else
                cp_commit();
            g_chunk(sb + (ch & 3) * G_STAGE, acc, arowb, browb, ua0, ub0, lr);
        }
    }

    float s1v[4], s2v[4];
    if (use_l1) {
        if (tid < G_TM) {
            float s = 0.0f;
#pragma unroll
            for (int p = 0; p < 16; ++p) s += g_l1part[p][b * SS + m0 + tid];
            s_red[tid] = s;
        }
        __syncthreads();
#pragma unroll
        for (int mf = 0; mf < 4; ++mf) {
            int rr = wm * 64 + mf * 16 + g;
            s1v[mf] = 1.0f / fmaxf(s_red[rr], 1e-12f);
            s2v[mf] = 1.0f / fmaxf(s_red[rr + 8], 1e-12f);
        }
        __syncthreads();
    } else {
#pragma unroll
        for (int mf = 0; mf < 4; ++mf) { s1v[mf] = 1.0f; s2v[mf] = 1.0f; }
    }

    if (final_out) {
        float* Co = C + (size_t)b * SS * DD;
#pragma unroll
        for (int mf = 0; mf < 4; ++mf) {
            int r1 = m0 + wm * 64 + mf * 16 + g;
            int r2 = r1 + 8;
#pragma unroll
            for (int nf = 0; nf < 8; ++nf) {
                int col = n0 + wn * 64 + nf * 8 + 2 * tg;
                *reinterpret_cast<float2*>(Co + (size_t)r1 * DD + col) =
                    make_float2(acc[mf][nf][0] * s1v[mf], acc[mf][nf][1] * s1v[mf]);
                *reinterpret_cast<float2*>(Co + (size_t)r2 * DD + col) =
                    make_float2(acc[mf][nf][2] * s2v[mf], acc[mf][nf][3] * s2v[mf]);
            }
        }
    } else {
        if (tid < G_TM) s_red[tid] = 0.0f;
        __syncthreads();
        __half* Mo = g_Mh + (size_t)b * SS * DD;
#pragma unroll
        for (int mf = 0; mf < 4; ++mf) {
            int r1 = m0 + wm * 64 + mf * 16 + g;
            int r2 = r1 + 8;
            float a1s = 0.0f, a2s = 0.0f;
#pragma unroll
            for (int nf = 0; nf < 8; ++nf) {
                int col = n0 + wn * 64 + nf * 8 + 2 * tg;
                __half2 h1 = __floats2half2_rn(acc[mf][nf][0] * s1v[mf],
                                               acc[mf][nf][1] * s1v[mf]);
                __half2 h2 = __floats2half2_rn(acc[mf][nf][2] * s2v[mf],
                                               acc[mf][nf][3] * s2v[mf]);
                *reinterpret_cast<__half2*>(Mo + (size_t)r1 * DD + col) = h1;
                *reinterpret_cast<__half2*>(Mo + (size_t)r2 * DD + col) = h2;
                float2 f1 = __half22float2(h1), f2 = __half22float2(h2);
                a1s += f1.x * f1.x + f1.y * f1.y;
                a2s += f2.x * f2.x + f2.y * f2.y;
            }
            a1s += __shfl_xor_sync(0xffffffffu, a1s, 1);
            a1s += __shfl_xor_sync(0xffffffffu, a1s, 2);
            a2s += __shfl_xor_sync(0xffffffffu, a2s, 1);
            a2s += __shfl_xor_sync(0xffffffffu, a2s, 2);
            if (tg == 0) {
                atomicAdd(&s_red[wm * 64 + mf * 16 + g], a1s);
                atomicAdd(&s_red[wm * 64 + mf * 16 + g + 8], a2s);
            }
        }
        __syncthreads();
        if (tid < G_TM)
            g_m2part[blockIdx.x][b * SS + m0 + tid] = s_red[tid];
    }
}

// ---------------------------------------------------------------------------
// wdist (R12 shape): W[i,j] = fp16(Ah/(dist+eps)); per-j-block l1 partials.
// CTA 128x128, 2 CTAs/SM.
// ---------------------------------------------------------------------------
__global__ void __launch_bounds__(NTHREADS, 2)
wdist_tc() {
    extern __shared__ uint32_t dyn[];
    float* s_red = (float*)((char*)dyn + W_PIPE);
    int tid = threadIdx.x;
    int wid = tid >> 5, lane = tid & 31;
    int wm = wid >> 2, wn = wid & 3;
    int g = lane >> 2, tg = lane & 3;
    uint32_t q = lane >> 3, lr = lane & 7;
    int b = blockIdx.z;
    int j0 = blockIdx.x * 128, i0 = blockIdx.y * 128;
    const __half* Mp = g_Mh + (size_t)b * SS * DD;
    const __half* Vp = g_Vh + (size_t)b * SS * DD;
    const __half* Ap = g_Ah + (size_t)b * SS * SS;
    __half* Wp = g_W + (size_t)b * SS * SS;
    const float* v2p = g_v2 + b * SS;

    uint32_t aoff[4], boff[2];
#pragma unroll
    for (int mf = 0; mf < 4; ++mf)
        aoff[mf] = ((wm * 64 + mf * 16 + (q & 1) * 8 + lr) * W_LDSH + (q >> 1) * 8) * 2;
#pragma unroll
    for (int p = 0; p < 2; ++p)
        boff[p] = ((wn * 32 + p * 16 + (q >> 1) * 8 + lr) * W_LDSH + (q & 1) * 8) * 2;

    float acc[4][4][4];
#pragma unroll
    for (int i = 0; i < 4; ++i)
#pragma unroll
        for (int j = 0; j < 4; ++j)
#pragma unroll
            for (int e = 0; e < 4; ++e) acc[i][j][e] = 0.0f;

    {
        uint32_t sb = smem_u32(dyn);
        w_issue(Mp, Vp, DD, DD, i0, j0, 0, sb, tid);
        w_issue(Mp, Vp, DD, DD, i0, j0, KC, sb + W_STAGE, tid);
        int nch = DD / KC;
        for (int ch = 0; ch < nch; ++ch) {
            cp_wait<1>();
            __syncthreads();
            if (ch + 2 < nch)
                w_issue(Mp, Vp, DD, DD, i0, j0, (ch + 2) * KC,
                        sb + ((ch + 2) % W_NSTAGE) * W_STAGE, tid);
            else
                cp_commit();
            w_chunk(sb + (ch % W_NSTAGE) * W_STAGE, acc, aoff, boff);
        }
    }

    if (tid < 128) {
        s_red[tid] = g_m2part[0][b * SS + i0 + tid] + g_m2part[1][b * SS + i0 + tid];
    }
    __syncthreads();
    float m21v[4], m22v[4];
#pragma unroll
    for (int mf = 0; mf < 4; ++mf) {
        int rr = wm * 64 + mf * 16 + g;
        m21v[mf] = s_red[rr];
        m22v[mf] = s_red[rr + 8];
    }
    __syncthreads();
    if (tid < 128) s_red[tid] = 0.0f;
    __syncthreads();

#pragma unroll
    for (int mf = 0; mf < 4; ++mf) {
        int r1 = i0 + wm * 64 + mf * 16 + g;
        int r2 = r1 + 8;
        float rs1 = 0.0f, rs2 = 0.0f;
#pragma unroll
        for (int nf = 0; nf < 4; ++nf) {
            int jj = j0 + wn * 32 + nf * 8 + 2 * tg;
            float v2a = v2p[jj], v2b = v2p[jj + 1];
            float2 a1 = __half22float2(
                *reinterpret_cast<const __half2*>(Ap + (size_t)r1 * SS + jj));
            float2 a2 = __half22float2(
                *reinterpret_cast<const __half2*>(Ap + (size_t)r2 * SS + jj));
            float d;
            d = sqrtf(fmaxf(m21v[mf] + v2a - 2.0f * acc[mf][nf][0], 0.0f));
            float w0 = a1.x * __frcp_rn(d + 0.01f);
            d = sqrtf(fmaxf(m21v[mf] + v2b - 2.0f * acc[mf][nf][1], 0.0f));
            float w1 = a1.y * __frcp_rn(d + 0.01f);
            d = sqrtf(fmaxf(m22v[mf] + v2a - 2.0f * acc[mf][nf][2], 0.0f));
            float w2 = a2.x * __frcp_rn(d + 0.01f);
            d = sqrtf(fmaxf(m22v[mf] + v2b - 2.0f * acc[mf][nf][3], 0.0f));
            float w3 = a2.y * __frcp_rn(d + 0.01f);
            __half2 h1 = __floats2half2_rn(w0, w1);
            __half2 h2 = __floats2half2_rn(w2, w3);
            float2 f1 = __half22float2(h1), f2 = __half22float2(h2);
            rs1 += fabsf(f1.x) + fabsf(f1.y);
            rs2 += fabsf(f2.x) + fabsf(f2.y);
            *reinterpret_cast<__half2*>(Wp + (size_t)r1 * SS + jj) = h1;
            *reinterpret_cast<__half2*>(Wp + (size_t)r2 * SS + jj) = h2;
        }
        rs1 += __shfl_xor_sync(0xffffffffu, rs1, 1);
        rs1 += __shfl_xor_sync(0xffffffffu, rs1, 2);
        rs2 += __shfl_xor_sync(0xffffffffu, rs2, 1);
        rs2 += __shfl_xor_sync(0xffffffffu, rs2, 2);
        if (tg == 0) {
            atomicAdd(&s_red[wm * 64 + mf * 16 + g], rs1);
            atomicAdd(&s_red[wm * 64 + mf * 16 + g + 8], rs2);
        }
    }
    __syncthreads();
    if (tid < 128)
        g_l1part[blockIdx.x][b * SS + i0 + tid] = s_red[tid];
}

// ---------------------------------------------------------------------------
extern "C" void kernel_launch(void* const* d_in, const int* in_sizes, int n_in,
                              void* d_out, int out_size) {
    const float* A = (const float*)d_in[0];  // (4, 2048, 2048)
    const float* V = (const float*)d_in[1];  // (4, 2048, 512)
    float* M = (float*)d_out;                // (4, 2048, 512)

    cudaFuncSetAttribute(gemm_tc, cudaFuncAttributeMaxDynamicSharedMemorySize, G_SMEM);
    cudaFuncSetAttribute(wdist_tc, cudaFuncAttributeMaxDynamicSharedMemorySize, W_SMEM);

    __half* g_Ah_p;  cudaGetSymbolAddress((void**)&g_Ah_p, g_Ah);

    dim3 ggrid(DD / G_TN, SS / G_TM, NB);   // (2, 16, 4)
    dim3 wgrid(SS / 128, SS / 128, NB);     // (16, 16, 4)

    int nA4 = NB * SS * SS / 4;
    round_kernel<<<1024, 256>>>(A, g_Ah_p, nA4 / 2);                     // #1
    round_kernel<<<1024, 256>>>(A + (size_t)nA4 / 2 * 4,
                                g_Ah_p + (size_t)nA4 / 2 * 4, nA4 / 2);  // #2
    prepV_kernel<<<dim3(SS / 32, NB), 256>>>(V);                         // #3
    gemm_tc<<<ggrid, NTHREADS, G_SMEM>>>(M, 0, 0, 0);                    // #4 (profiled)
    for (int it = 0; it < 3; ++it) {
        wdist_tc<<<wgrid, NTHREADS, W_SMEM>>>();
        gemm_tc<<<ggrid, NTHREADS, G_SMEM>>>(M, 1, 1, it == 2);
    }
}

// round 17
// speedup vs baseline: 1.2618x; 1.0594x over previous
#include <cuda_runtime.h>
#include <cuda_fp16.h>
#include <math.h>
#include <stdint.h>

#define SS 2048
#define DD 512
#define NB 4
#define NTHREADS 256

// ---- gemm config: CTA 128x256, warp tile 64x64, XOR-swizzled 128B rows, KC=64
#define G_KC 64
#define G_TM 128
#define G_TN 256
#define G_XTILE (G_TM * 128)
#define G_YTILE (G_TN * 128)
#define G_STAGE (G_XTILE + G_YTILE)          // 49152
#define G_NSTAGE 4
#define G_PIPE (G_NSTAGE * G_STAGE)
#define G_SMEM (G_PIPE + 512)

// ---- wdist config: CTA 128x128, warp tile 64x32, KC=32, LDSH=40, + A prefetch
#define W_KC 32
#define W_LDSH 40
#define W_XTILE (128 * W_LDSH * 2)           // 10240
#define W_STAGE (2 * W_XTILE)                // 20480
#define W_NSTAGE 3
#define W_PIPE (W_NSTAGE * W_STAGE)          // 61440
#define W_ATILE (128 * 128 * 2)              // 32768 (A tile fp16)
#define W_SMEM (W_PIPE + W_ATILE + 512)      // 94720 -> 2 CTAs/SM

// ---------------- scratch (allocation-free device globals, fp16) ----------
__device__ __half g_W[(size_t)NB * SS * SS];
__device__ __half g_Ah[(size_t)NB * SS * SS];
__device__ __half g_Vh[(size_t)NB * SS * DD];
__device__ __half g_VTh[(size_t)NB * DD * SS];
__device__ __half g_Mh[(size_t)NB * SS * DD];
__device__ float g_v2[NB * SS];
__device__ float g_m2part[2][NB * SS];
__device__ float g_l1part[16][NB * SS];

// ---------------- helpers ----------------
__device__ __forceinline__ uint32_t smem_u32(const void* p) {
    uint32_t a;
    asm("{ .reg .u64 t; cvta.to.shared.u64 t, %1; cvt.u32.u64 %0, t; }"
        : "=r"(a) : "l"(p));
    return a;
}
__device__ __forceinline__ void cp16(uint32_t saddr, const void* gaddr) {
    asm volatile("cp.async.cg.shared.global [%0], [%1], 16;"
                 :: "r"(saddr), "l"(gaddr) : "memory");
}
__device__ __forceinline__ void cp_commit() {
    asm volatile("cp.async.commit_group;" ::: "memory");
}
template <int N>
__device__ __forceinline__ void cp_wait() {
    asm volatile("cp.async.wait_group %0;" :: "n"(N) : "memory");
}
__device__ __forceinline__ void ldsm4(uint32_t* r, uint32_t addr) {
    asm volatile("ldmatrix.sync.aligned.m8n8.x4.shared.b16 {%0,%1,%2,%3}, [%4];"
                 : "=r"(r[0]), "=r"(r[1]), "=r"(r[2]), "=r"(r[3]) : "r"(addr));
}
__device__ __forceinline__ void mma_f16(float* c, const uint32_t* a, const uint32_t* b) {
    asm volatile(
        "mma.sync.aligned.m16n8k16.row.col.f32.f16.f16.f32 "
        "{%0,%1,%2,%3}, {%4,%5,%6,%7}, {%8,%9}, {%0,%1,%2,%3};"
        : "+f"(c[0]), "+f"(c[1]), "+f"(c[2]), "+f"(c[3])
        : "r"(a[0]), "r"(a[1]), "r"(a[2]), "r"(a[3]), "r"(b[0]), "r"(b[1]));
}

// ===========================================================================
// GEMM-side pipeline: XOR-swizzle, warp tile 64x64, fragment double-buffer
// ===========================================================================
__device__ __forceinline__ void g_issue(const __half* __restrict__ X,
                                        const __half* __restrict__ Y,
                                        int ldx, int ldy, int m0, int n0,
                                        int k0, uint32_t sbuf, int tid) {
#pragma unroll
    for (int p = 0; p < G_TM * 8 / NTHREADS; ++p) {
        int idx = tid + p * NTHREADS;
        int row = idx >> 3, q = idx & 7;
        cp16(sbuf + row * 128 + ((q ^ (row & 7)) << 4),
             X + (size_t)(m0 + row) * ldx + k0 + q * 8);
    }
    uint32_t ybuf = sbuf + G_XTILE;
#pragma unroll
    for (int p = 0; p < G_TN * 8 / NTHREADS; ++p) {
        int idx = tid + p * NTHREADS;
        int row = idx >> 3, q = idx & 7;
        cp16(ybuf + row * 128 + ((q ^ (row & 7)) << 4),
             Y + (size_t)(n0 + row) * ldy + k0 + q * 8);
    }
    cp_commit();
}

__device__ __forceinline__ void g_ldfrags(uint32_t xs, uint32_t ys, int ks,
                                          const uint32_t* arowb, const uint32_t* browb,
                                          uint32_t ua0, uint32_t ub0, uint32_t lr,
                                          uint32_t af[4][4], uint32_t bf[8][2]) {
    uint32_t ua = (((ua0 + 2 * ks) ^ lr) << 4);
    uint32_t ub = (((ub0 + 2 * ks) ^ lr) << 4);
#pragma unroll
    for (int mf = 0; mf < 4; ++mf) ldsm4(af[mf], xs + arowb[mf] + ua);
#pragma unroll
    for (int p = 0; p < 4; ++p) {
        uint32_t r[4];
        ldsm4(r, ys + browb[p] + ub);
        bf[2 * p][0] = r[0];
        bf[2 * p][1] = r[1];
        bf[2 * p + 1][0] = r[2];
        bf[2 * p + 1][1] = r[3];
    }
}

__device__ __forceinline__ void g_chunk(uint32_t sb, float acc[4][8][4],
                                        const uint32_t* arowb, const uint32_t* browb,
                                        uint32_t ua0, uint32_t ub0, uint32_t lr) {
    uint32_t ys = sb + G_XTILE;
    uint32_t af[2][4][4], bf[2][8][2];
    g_ldfrags(sb, ys, 0, arowb, browb, ua0, ub0, lr, af[0], bf[0]);
#pragma unroll
    for (int ks = 0; ks < 4; ++ks) {
        int cur = ks & 1, nxt = cur ^ 1;
        if (ks < 3)
            g_ldfrags(sb, ys, ks + 1, arowb, browb, ua0, ub0, lr, af[nxt], bf[nxt]);
#pragma unroll
        for (int mf = 0; mf < 4; ++mf)
#pragma unroll
            for (int nf = 0; nf < 8; ++nf)
                mma_f16(acc[mf][nf], af[cur][mf], bf[cur][nf]);
    }
}

// ===========================================================================
// wdist-side pipeline: padded LDSH=40, KC=32, warp tile 64x32
// ===========================================================================
__device__ __forceinline__ void w_issue(const __half* __restrict__ X,
                                        const __half* __restrict__ Y,
                                        int m0, int n0, int k0,
                                        uint32_t sbuf, int tid) {
#pragma unroll
    for (int p = 0; p < 2; ++p) {
        int idx = tid + p * NTHREADS;
        int row = idx >> 2, q = idx & 3;
        cp16(sbuf + (row * W_LDSH + q * 8) * 2,
             X + (size_t)(m0 + row) * DD + k0 + q * 8);
    }
    uint32_t ybuf = sbuf + W_XTILE;
#pragma unroll
    for (int p = 0; p < 2; ++p) {
        int idx = tid + p * NTHREADS;
        int row = idx >> 2, q = idx & 3;
        cp16(ybuf + (row * W_LDSH + q * 8) * 2,
             Y + (size_t)(n0 + row) * DD + k0 + q * 8);
    }
    cp_commit();
}

__device__ __forceinline__ void w_chunk(uint32_t sb, float acc[4][4][4],
                                        const uint32_t* aoff, const uint32_t* boff) {
    uint32_t ys = sb + W_XTILE;
#pragma unroll
    for (int ks = 0; ks < 2; ++ks) {
        uint32_t kb = ks * 16 * 2;
        uint32_t af[4][4], bf[4][2];
#pragma unroll
        for (int mf = 0; mf < 4; ++mf) ldsm4(af[mf], sb + aoff[mf] + kb);
#pragma unroll
        for (int p = 0; p < 2; ++p) {
            uint32_t r[4];
            ldsm4(r, ys + boff[p] + kb);
            bf[2 * p][0] = r[0];
            bf[2 * p][1] = r[1];
            bf[2 * p + 1][0] = r[2];
            bf[2 * p + 1][1] = r[3];
        }
#pragma unroll
        for (int mf = 0; mf < 4; ++mf)
#pragma unroll
            for (int nf = 0; nf < 4; ++nf)
                mma_f16(acc[mf][nf], af[mf], bf[nf]);
    }
}

// ---------------------------------------------------------------------------
// Elementwise round fp32 -> fp16.
// ---------------------------------------------------------------------------
__global__ void round_kernel(const float* __restrict__ in, __half* __restrict__ out,
                             int n4) {
    int i = blockIdx.x * blockDim.x + threadIdx.x;
    int stride = gridDim.x * blockDim.x;
    for (; i < n4; i += stride) {
        float4 v = reinterpret_cast<const float4*>(in)[i];
        __half2* o = reinterpret_cast<__half2*>(out) + 2 * i;
        o[0] = __floats2half2_rn(v.x, v.y);
        o[1] = __floats2half2_rn(v.z, v.w);
    }
}

// ---------------------------------------------------------------------------
// Fused V prep: g_Vh = round(V); g_VTh[d][s] = round(V[s][d]); g_v2.
// ---------------------------------------------------------------------------
__global__ void prepV_kernel(const float* __restrict__ V) {
    __shared__ float t[32][33];
    int b = blockIdx.y;
    int s0 = blockIdx.x * 32;
    const float* Vp = V + (size_t)b * SS * DD;
    __half* Vh = g_Vh + (size_t)b * SS * DD;
    __half* Tp = g_VTh + (size_t)b * DD * SS;
    int tx = threadIdx.x & 31, ty = threadIdx.x >> 5;
    float vsum[4] = {0.f, 0.f, 0.f, 0.f};
    for (int dt = 0; dt < DD / 32; ++dt) {
#pragma unroll
        for (int j = 0; j < 4; ++j) {
            int i = ty + 8 * j;
            float v = Vp[(size_t)(s0 + i) * DD + dt * 32 + tx];
            __half h = __float2half_rn(v);
            float vr = __half2float(h);
            t[i][tx] = vr;
            vsum[j] += vr * vr;
            Vh[(size_t)(s0 + i) * DD + dt * 32 + tx] = h;
        }
        __syncthreads();
#pragma unroll
        for (int j = 0; j < 4; ++j) {
            int i = ty + 8 * j;
            Tp[(size_t)(dt * 32 + i) * SS + s0 + tx] = __float2half_rn(t[tx][i]);
        }
        __syncthreads();
    }
#pragma unroll
    for (int j = 0; j < 4; ++j) {
#pragma unroll
        for (int o = 16; o > 0; o >>= 1)
            vsum[j] += __shfl_down_sync(0xffffffffu, vsum[j], o);
        if (tx == 0) g_v2[b * SS + s0 + ty + 8 * j] = vsum[j];
    }
}

// ---------------------------------------------------------------------------
// GEMM: out[m,n] = scale(m) * sum_k X[m,k]*VTh[n,k]
// ---------------------------------------------------------------------------
__global__ void __launch_bounds__(NTHREADS, 1)
gemm_tc(float* __restrict__ C, int use_w, int use_l1, int final_out) {
    extern __shared__ uint32_t dyn[];
    float* s_red = (float*)((char*)dyn + G_PIPE);
    int tid = threadIdx.x;
    int wid = tid >> 5, lane = tid & 31;
    int wm = wid >> 2, wn = wid & 3;
    int g = lane >> 2, tg = lane & 3;
    uint32_t q = lane >> 3, lr = lane & 7;
    int b = blockIdx.z;
    int n0 = blockIdx.x * G_TN, m0 = blockIdx.y * G_TM;
    const __half* X = (use_w ? g_W : g_Ah) + (size_t)b * SS * SS;
    const __half* Y = g_VTh + (size_t)b * DD * SS;

    uint32_t arowb[4], browb[4];
#pragma unroll
    for (int mf = 0; mf < 4; ++mf)
        arowb[mf] = (wm * 64 + mf * 16 + (q & 1) * 8 + lr) * 128;
#pragma unroll
    for (int p = 0; p < 4; ++p)
        browb[p] = (wn * 64 + p * 16 + (q >> 1) * 8 + lr) * 128;
    uint32_t ua0 = q >> 1, ub0 = q & 1;

    float acc[4][8][4];
#pragma unroll
    for (int i = 0; i < 4; ++i)
#pragma unroll
        for (int j = 0; j < 8; ++j)
#pragma unroll
            for (int e = 0; e < 4; ++e) acc[i][j][e] = 0.0f;

    {
        uint32_t sb = smem_u32(dyn);
        g_issue(X, Y, SS, SS, m0, n0, 0, sb, tid);
        g_issue(X, Y, SS, SS, m0, n0, G_KC, sb + G_STAGE, tid);
        g_issue(X, Y, SS, SS, m0, n0, 2 * G_KC, sb + 2 * G_STAGE, tid);
        int nch = SS / G_KC;
        for (int ch = 0; ch < nch; ++ch) {
            cp_wait<2>();
            __syncthreads();
            if (ch + 3 < nch)
                g_issue(X, Y, SS, SS, m0, n0, (ch + 3) * G_KC,
                        sb + ((ch + 3) & 3) * G_STAGE, tid);
            else
                cp_commit();
            g_chunk(sb + (ch & 3) * G_STAGE, acc, arowb, browb, ua0, ub0, lr);
        }
    }

    float s1v[4], s2v[4];
    if (use_l1) {
        if (tid < G_TM) {
            float s = 0.0f;
#pragma unroll
            for (int p = 0; p < 16; ++p) s += g_l1part[p][b * SS + m0 + tid];
            s_red[tid] = s;
        }
        __syncthreads();
#pragma unroll
        for (int mf = 0; mf < 4; ++mf) {
            int rr = wm * 64 + mf * 16 + g;
            s1v[mf] = 1.0f / fmaxf(s_red[rr], 1e-12f);
            s2v[mf] = 1.0f / fmaxf(s_red[rr + 8], 1e-12f);
        }
        __syncthreads();
    } else {
#pragma unroll
        for (int mf = 0; mf < 4; ++mf) { s1v[mf] = 1.0f; s2v[mf] = 1.0f; }
    }

    if (final_out) {
        float* Co = C + (size_t)b * SS * DD;
#pragma unroll
        for (int mf = 0; mf < 4; ++mf) {
            int r1 = m0 + wm * 64 + mf * 16 + g;
            int r2 = r1 + 8;
#pragma unroll
            for (int nf = 0; nf < 8; ++nf) {
                int col = n0 + wn * 64 + nf * 8 + 2 * tg;
                *reinterpret_cast<float2*>(Co + (size_t)r1 * DD + col) =
                    make_float2(acc[mf][nf][0] * s1v[mf], acc[mf][nf][1] * s1v[mf]);
                *reinterpret_cast<float2*>(Co + (size_t)r2 * DD + col) =
                    make_float2(acc[mf][nf][2] * s2v[mf], acc[mf][nf][3] * s2v[mf]);
            }
        }
    } else {
        if (tid < G_TM) s_red[tid] = 0.0f;
        __syncthreads();
        __half* Mo = g_Mh + (size_t)b * SS * DD;
#pragma unroll
        for (int mf = 0; mf < 4; ++mf) {
            int r1 = m0 + wm * 64 + mf * 16 + g;
            int r2 = r1 + 8;
            float a1s = 0.0f, a2s = 0.0f;
#pragma unroll
            for (int nf = 0; nf < 8; ++nf) {
                int col = n0 + wn * 64 + nf * 8 + 2 * tg;
                __half2 h1 = __floats2half2_rn(acc[mf][nf][0] * s1v[mf],
                                               acc[mf][nf][1] * s1v[mf]);
                __half2 h2 = __floats2half2_rn(acc[mf][nf][2] * s2v[mf],
                                               acc[mf][nf][3] * s2v[mf]);
                *reinterpret_cast<__half2*>(Mo + (size_t)r1 * DD + col) = h1;
                *reinterpret_cast<__half2*>(Mo + (size_t)r2 * DD + col) = h2;
                float2 f1 = __half22float2(h1), f2 = __half22float2(h2);
                a1s += f1.x * f1.x + f1.y * f1.y;
                a2s += f2.x * f2.x + f2.y * f2.y;
            }
            a1s += __shfl_xor_sync(0xffffffffu, a1s, 1);
            a1s += __shfl_xor_sync(0xffffffffu, a1s, 2);
            a2s += __shfl_xor_sync(0xffffffffu, a2s, 1);
            a2s += __shfl_xor_sync(0xffffffffu, a2s, 2);
            if (tg == 0) {
                atomicAdd(&s_red[wm * 64 + mf * 16 + g], a1s);
                atomicAdd(&s_red[wm * 64 + mf * 16 + g + 8], a2s);
            }
        }
        __syncthreads();
        if (tid < G_TM)
            g_m2part[blockIdx.x][b * SS + m0 + tid] = s_red[tid];
    }
}

// ---------------------------------------------------------------------------
// wdist: W[i,j] = fp16(Ah/(dist+eps)); A prefetched to smem; W staged through
// smem for coalesced writeout; per-j-block l1 partials. 2 CTAs/SM.
// ---------------------------------------------------------------------------
__global__ void __launch_bounds__(NTHREADS, 2)
wdist_tc() {
    extern __shared__ uint32_t dyn[];
    __half* sA = (__half*)((char*)dyn + W_PIPE);
    float* s_red = (float*)((char*)dyn + W_PIPE + W_ATILE);
    int tid = threadIdx.x;
    int wid = tid >> 5, lane = tid & 31;
    int wm = wid >> 2, wn = wid & 3;
    int g = lane >> 2, tg = lane & 3;
    uint32_t q = lane >> 3, lr = lane & 7;
    int b = blockIdx.z;
    int j0 = blockIdx.x * 128, i0 = blockIdx.y * 128;
    const __half* Mp = g_Mh + (size_t)b * SS * DD;
    const __half* Vp = g_Vh + (size_t)b * SS * DD;
    const __half* Ap = g_Ah + (size_t)b * SS * SS;
    __half* Wp = g_W + (size_t)b * SS * SS;
    const float* v2p = g_v2 + b * SS;

    uint32_t aoff[4], boff[2];
#pragma unroll
    for (int mf = 0; mf < 4; ++mf)
        aoff[mf] = ((wm * 64 + mf * 16 + (q & 1) * 8 + lr) * W_LDSH + (q >> 1) * 8) * 2;
#pragma unroll
    for (int p = 0; p < 2; ++p)
        boff[p] = ((wn * 32 + p * 16 + (q >> 1) * 8 + lr) * W_LDSH + (q & 1) * 8) * 2;

    float acc[4][4][4];
#pragma unroll
    for (int i = 0; i < 4; ++i)
#pragma unroll
        for (int j = 0; j < 4; ++j)
#pragma unroll
            for (int e = 0; e < 4; ++e) acc[i][j][e] = 0.0f;

    {
        uint32_t sb = smem_u32(dyn);
        // A-tile prefetch group (drains before chunk groups; in-order completion)
        uint32_t sAu = sb + W_PIPE;
#pragma unroll
        for (int p = 0; p < 8; ++p) {
            int idx = tid + p * NTHREADS;
            int row = idx >> 4, c16 = idx & 15;
            cp16(sAu + row * 256 + c16 * 16,
                 Ap + (size_t)(i0 + row) * SS + j0 + c16 * 8);
        }
        cp_commit();
        w_issue(Mp, Vp, i0, j0, 0, sb, tid);
        w_issue(Mp, Vp, i0, j0, W_KC, sb + W_STAGE, tid);
        int nch = DD / W_KC;  // 16
        for (int ch = 0; ch < nch; ++ch) {
            cp_wait<1>();
            __syncthreads();
            if (ch + 2 < nch)
                w_issue(Mp, Vp, i0, j0, (ch + 2) * W_KC,
                        sb + ((ch + 2) % W_NSTAGE) * W_STAGE, tid);
            else
                cp_commit();
            w_chunk(sb + (ch % W_NSTAGE) * W_STAGE, acc, aoff, boff);
        }
    }

    // m2 gather
    if (tid < 128)
        s_red[tid] = g_m2part[0][b * SS + i0 + tid] + g_m2part[1][b * SS + i0 + tid];
    __syncthreads();
    float m21v[4], m22v[4];
#pragma unroll
    for (int mf = 0; mf < 4; ++mf) {
        int rr = wm * 64 + mf * 16 + g;
        m21v[mf] = s_red[rr];
        m22v[mf] = s_red[rr + 8];
    }
    __syncthreads();
    if (tid < 128) s_red[tid] = 0.0f;
    __syncthreads();

    // compute w from smem A, stage into smem W tile (reuse pipe stages 0-1)
    __half* sW = (__half*)dyn;
#pragma unroll
    for (int mf = 0; mf < 4; ++mf) {
        int lr1 = wm * 64 + mf * 16 + g;   // local rows
        int lr2 = lr1 + 8;
        float rs1 = 0.0f, rs2 = 0.0f;
#pragma unroll
        for (int nf = 0; nf < 4; ++nf) {
            int lj = wn * 32 + nf * 8 + 2 * tg;   // local col
            int jj = j0 + lj;
            float v2a = v2p[jj], v2b = v2p[jj + 1];
            float2 a1 = __half22float2(
                *reinterpret_cast<const __half2*>(sA + lr1 * 128 + lj));
            float2 a2 = __half22float2(
                *reinterpret_cast<const __half2*>(sA + lr2 * 128 + lj));
            float d;
            d = sqrtf(fmaxf(m21v[mf] + v2a - 2.0f * acc[mf][nf][0], 0.0f));
            float w0 = a1.x * __frcp_rn(d + 0.01f);
            d = sqrtf(fmaxf(m21v[mf] + v2b - 2.0f * acc[mf][nf][1], 0.0f));
            float w1 = a1.y * __frcp_rn(d + 0.01f);
            d = sqrtf(fmaxf(m22v[mf] + v2a - 2.0f * acc[mf][nf][2], 0.0f));
            float w2 = a2.x * __frcp_rn(d + 0.01f);
            d = sqrtf(fmaxf(m22v[mf] + v2b - 2.0f * acc[mf][nf][3], 0.0f));
            float w3 = a2.y * __frcp_rn(d + 0.01f);
            __half2 h1 = __floats2half2_rn(w0, w1);
            __half2 h2 = __floats2half2_rn(w2, w3);
            float2 f1 = __half22float2(h1), f2 = __half22float2(h2);
            rs1 += fabsf(f1.x) + fabsf(f1.y);
            rs2 += fabsf(f2.x) + fabsf(f2.y);
            *reinterpret_cast<__half2*>(sW + lr1 * 128 + lj) = h1;
            *reinterpret_cast<__half2*>(sW + lr2 * 128 + lj) = h2;
        }
        rs1 += __shfl_xor_sync(0xffffffffu, rs1, 1);
        rs1 += __shfl_xor_sync(0xffffffffu, rs1, 2);
        rs2 += __shfl_xor_sync(0xffffffffu, rs2, 1);
        rs2 += __shfl_xor_sync(0xffffffffu, rs2, 2);
        if (tg == 0) {
            atomicAdd(&s_red[wm * 64 + mf * 16 + g], rs1);
            atomicAdd(&s_red[wm * 64 + mf * 16 + g + 8], rs2);
        }
    }
    __syncthreads();

    // coalesced W writeout: 16B per thread-chunk
#pragma unroll
    for (int p = 0; p < 8; ++p) {
        int idx = tid + p * NTHREADS;
        int row = idx >> 4, c16 = idx & 15;
        uint4 v = *reinterpret_cast<const uint4*>(sW + row * 128 + c16 * 8);
        *reinterpret_cast<uint4*>(Wp + (size_t)(i0 + row) * SS + j0 + c16 * 8) = v;
    }
    if (tid < 128)
        g_l1part[blockIdx.x][b * SS + i0 + tid] = s_red[tid];
}

// ---------------------------------------------------------------------------
extern "C" void kernel_launch(void* const* d_in, const int* in_sizes, int n_in,
                              void* d_out, int out_size) {
    const float* A = (const float*)d_in[0];  // (4, 2048, 2048)
    const float* V = (const float*)d_in[1];  // (4, 2048, 512)
    float* M = (float*)d_out;                // (4, 2048, 512)

    cudaFuncSetAttribute(gemm_tc, cudaFuncAttributeMaxDynamicSharedMemorySize, G_SMEM);
    cudaFuncSetAttribute(wdist_tc, cudaFuncAttributeMaxDynamicSharedMemorySize, W_SMEM);

    __half* g_Ah_p;  cudaGetSymbolAddress((void**)&g_Ah_p, g_Ah);

    dim3 ggrid(DD / G_TN, SS / G_TM, NB);   // (2, 16, 4)
    dim3 wgrid(SS / 128, SS / 128, NB);     // (16, 16, 4)

    round_kernel<<<2048, 256>>>(A, g_Ah_p, NB * SS * SS / 4);    // #1
    prepV_kernel<<<dim3(SS / 32, NB), 256>>>(V);                 // #2
    gemm_tc<<<ggrid, NTHREADS, G_SMEM>>>(M, 0, 0, 0);            // #3
    for (int it = 0; it < 3; ++it) {
        wdist_tc<<<wgrid, NTHREADS, W_SMEM>>>();                 // #4: profiled
        gemm_tc<<<ggrid, NTHREADS, G_SMEM>>>(M, 1, 1, it == 2);
    }
}